// round 1
// baseline (speedup 1.0000x reference)
#include <cuda_runtime.h>

#define Nn 16384
#define Tt 4
#define Hh 64
#define Ee 262144
#define NT (Nn*Tt)
#define NEG_SLOPE 0.2f
#define LN_EPS 1e-5f

// -------- scratch (static device globals; no allocation) --------
__device__ __align__(16) float g_h[NT*Hh];       // per-conv transformed features
__device__ __align__(16) float g_logits[NT];     // per-conv leaky(dot(h,a)), layout [N][T]
__device__ __align__(16) float g_alpha[Ee*Tt];   // per-conv alpha in CSR order
__device__ __align__(16) float g_msum[NT*Hh];    // ms + mf accumulator
__device__ __align__(16) float g_xbuf[NT*Hh];    // layer-0 output / layer-1 input
__device__ int g_off[2][Nn+1];
__device__ int g_cnt[2][Nn];
__device__ int g_csr[2][Ee];

// ---------------- CSR build ----------------
__global__ void k_zero_counts() {
    int i = blockIdx.x*blockDim.x + threadIdx.x;
    if (i < 2*Nn) ((int*)g_cnt)[i] = 0;
}

__global__ void k_count(const int* __restrict__ ei, int which) {
    int e = blockIdx.x*blockDim.x + threadIdx.x;
    if (e < Ee) atomicAdd(&g_cnt[which][ei[Ee + e]], 1);
}

__global__ void k_scan(int which) {
    __shared__ int sh[1024];
    int tid = threadIdx.x;
    int base = tid * 16;
    int local[16];
    int s = 0;
    #pragma unroll
    for (int j = 0; j < 16; j++) { local[j] = s; s += g_cnt[which][base + j]; }
    sh[tid] = s;
    __syncthreads();
    for (int off = 1; off < 1024; off <<= 1) {
        int v = (tid >= off) ? sh[tid - off] : 0;
        __syncthreads();
        sh[tid] += v;
        __syncthreads();
    }
    int pre = (tid == 0) ? 0 : sh[tid - 1];
    #pragma unroll
    for (int j = 0; j < 16; j++) {
        g_off[which][base + j] = pre + local[j];
        g_cnt[which][base + j] = 0;   // re-zero: becomes fill cursor
    }
    if (tid == 1023) g_off[which][Nn] = sh[1023];
}

__global__ void k_fill(const int* __restrict__ ei, int which) {
    int e = blockIdx.x*blockDim.x + threadIdx.x;
    if (e >= Ee) return;
    int src = ei[e];
    int dst = ei[Ee + e];
    int pos = g_off[which][dst] + atomicAdd(&g_cnt[which][dst], 1);
    g_csr[which][pos] = src;
}

// ---------------- GEMM h = x @ W, fused logits = leaky(h . a) ----------------
// block: 64 rows x 64 cols; blockDim (16,16); each thread 4 rows x 4 cols.
__global__ void k_gemm_logits(const float* __restrict__ x,
                              const float* __restrict__ W,
                              const float* __restrict__ a) {
    __shared__ float xs[64*65];
    __shared__ float ws[64*64];
    __shared__ float as_[64];
    const int tx = threadIdx.x;            // 0..15 (col group)
    const int ty = threadIdx.y;            // 0..15 (row group)
    const int tid = ty*16 + tx;
    const int rowBase = blockIdx.x * 64;

    // load W (16KB, contiguous) vectorized
    const float4* W4 = (const float4*)W;
    float4* ws4 = (float4*)ws;
    #pragma unroll
    for (int i = tid; i < 1024; i += 256) ws4[i] = W4[i];
    if (tid < 64) as_[tid] = a[tid];
    // load x tile into padded smem (coalesced global, padded to kill bank conflicts)
    #pragma unroll
    for (int i = 0; i < 16; i++) {
        int idx = i*256 + tid;
        int r = idx >> 6, k = idx & 63;
        xs[r*65 + k] = x[rowBase*64 + idx];
    }
    __syncthreads();

    const int c0 = tx*4, r0 = ty*4;
    float acc[4][4] = {};
    #pragma unroll 8
    for (int k = 0; k < 64; k++) {
        float4 w = *(const float4*)(&ws[k*64 + c0]);
        float x0 = xs[(r0+0)*65 + k];
        float x1 = xs[(r0+1)*65 + k];
        float x2 = xs[(r0+2)*65 + k];
        float x3 = xs[(r0+3)*65 + k];
        acc[0][0] += x0*w.x; acc[0][1] += x0*w.y; acc[0][2] += x0*w.z; acc[0][3] += x0*w.w;
        acc[1][0] += x1*w.x; acc[1][1] += x1*w.y; acc[1][2] += x1*w.z; acc[1][3] += x1*w.w;
        acc[2][0] += x2*w.x; acc[2][1] += x2*w.y; acc[2][2] += x2*w.z; acc[2][3] += x2*w.w;
        acc[3][0] += x3*w.x; acc[3][1] += x3*w.y; acc[3][2] += x3*w.z; acc[3][3] += x3*w.w;
    }

    float pdot[4];
    #pragma unroll
    for (int i = 0; i < 4; i++) {
        float4 v = make_float4(acc[i][0], acc[i][1], acc[i][2], acc[i][3]);
        *(float4*)(&g_h[(rowBase + r0 + i)*64 + c0]) = v;
        pdot[i] = acc[i][0]*as_[c0] + acc[i][1]*as_[c0+1]
                + acc[i][2]*as_[c0+2] + acc[i][3]*as_[c0+3];
    }
    // reduce partial dot across the 16 col-group lanes (width-16 segments in a warp)
    #pragma unroll
    for (int off = 8; off > 0; off >>= 1) {
        #pragma unroll
        for (int i = 0; i < 4; i++)
            pdot[i] += __shfl_down_sync(0xffffffffu, pdot[i], off, 16);
    }
    if (tx == 0) {
        #pragma unroll
        for (int i = 0; i < 4; i++) {
            float v = pdot[i];
            g_logits[rowBase + r0 + i] = (v > 0.f) ? v : NEG_SLOPE * v;
        }
    }
}

// ---------------- per-node softmax: m, den, then alpha in CSR order ----------------
__global__ void k_softmax_alpha(int which) {
    int n = blockIdx.x*blockDim.x + threadIdx.x;
    if (n >= Nn) return;
    int rs = g_off[which][n], re = g_off[which][n+1];
    if (rs == re) return;
    const int* __restrict__ srcs = g_csr[which];
    float4 mx = make_float4(-1e30f, -1e30f, -1e30f, -1e30f);
    for (int p = rs; p < re; p++) {
        int s = srcs[p];
        float4 lg = *(const float4*)&g_logits[s*4];
        mx.x = fmaxf(mx.x, lg.x); mx.y = fmaxf(mx.y, lg.y);
        mx.z = fmaxf(mx.z, lg.z); mx.w = fmaxf(mx.w, lg.w);
    }
    float4 den = make_float4(0.f, 0.f, 0.f, 0.f);
    for (int p = rs; p < re; p++) {
        int s = srcs[p];
        float4 lg = *(const float4*)&g_logits[s*4];
        den.x += __expf(lg.x - mx.x); den.y += __expf(lg.y - mx.y);
        den.z += __expf(lg.z - mx.z); den.w += __expf(lg.w - mx.w);
    }
    float4 rd = make_float4(1.f/den.x, 1.f/den.y, 1.f/den.z, 1.f/den.w);
    for (int p = rs; p < re; p++) {
        int s = srcs[p];
        float4 lg = *(const float4*)&g_logits[s*4];
        float4 al;
        al.x = __expf(lg.x - mx.x) * rd.x;
        al.y = __expf(lg.y - mx.y) * rd.y;
        al.z = __expf(lg.z - mx.z) * rd.z;
        al.w = __expf(lg.w - mx.w) * rd.w;
        *(float4*)&g_alpha[p*4] = al;
    }
}

// ---------------- aggregation: msum[dst] (+)= sum_e alpha * h[src] ----------------
// blockDim (64,4): 4 nodes per block, 64 h-lanes, register accumulation, no atomics.
__global__ void k_aggregate(int which, int first) {
    int node = blockIdx.x*4 + threadIdx.y;
    int hh = threadIdx.x;
    int rs = g_off[which][node], re = g_off[which][node+1];
    const int* __restrict__ srcs = g_csr[which];
    float a0 = 0.f, a1 = 0.f, a2 = 0.f, a3 = 0.f;
    for (int p = rs; p < re; p++) {
        int s = srcs[p];
        float4 al = *(const float4*)&g_alpha[p*4];
        const float* __restrict__ hr = &g_h[s*256];
        a0 += al.x * hr[hh];
        a1 += al.y * hr[64  + hh];
        a2 += al.z * hr[128 + hh];
        a3 += al.w * hr[192 + hh];
    }
    float* o = &g_msum[node*256];
    if (first) {
        o[hh] = a0; o[64+hh] = a1; o[128+hh] = a2; o[192+hh] = a3;
    } else {
        o[hh] += a0; o[64+hh] += a1; o[128+hh] += a2; o[192+hh] += a3;
    }
}

// ---------------- LayerNorm(x + 0.5*msum) ----------------
// warp per row of 64; blockDim (32,8)
__global__ void k_ln(const float* __restrict__ xin,
                     const float* __restrict__ g,
                     const float* __restrict__ b,
                     float* __restrict__ out) {
    int row = blockIdx.x*8 + threadIdx.y;
    int lane = threadIdx.x;
    float2 xi = *(const float2*)&xin[row*64 + lane*2];
    float2 ms = *(const float2*)&g_msum[row*64 + lane*2];
    float v0 = xi.x + 0.5f*ms.x;
    float v1 = xi.y + 0.5f*ms.y;
    float s = v0 + v1, sq = v0*v0 + v1*v1;
    #pragma unroll
    for (int off = 16; off > 0; off >>= 1) {
        s  += __shfl_xor_sync(0xffffffffu, s,  off);
        sq += __shfl_xor_sync(0xffffffffu, sq, off);
    }
    float mean = s * (1.f/64.f);
    float var  = sq * (1.f/64.f) - mean*mean;
    float rstd = rsqrtf(var + LN_EPS);
    float2 gg = *(const float2*)&g[lane*2];
    float2 bb = *(const float2*)&b[lane*2];
    float2 o;
    o.x = (v0 - mean)*rstd*gg.x + bb.x;
    o.y = (v1 - mean)*rstd*gg.y + bb.y;
    *(float2*)&out[row*64 + lane*2] = o;
}

// ---------------- launch ----------------
static void run_conv(const float* x, const float* W, const float* a, int which, int first) {
    k_gemm_logits<<<NT/64, dim3(16,16)>>>(x, W, a);
    k_softmax_alpha<<<Nn/256, 256>>>(which);
    k_aggregate<<<Nn/4, dim3(64,4)>>>(which, first);
}

extern "C" void kernel_launch(void* const* d_in, const int* in_sizes, int n_in,
                              void* d_out, int out_size) {
    const float* pred = (const float*)d_in[0];
    const int*   eis  = (const int*)d_in[1];
    const int*   eif  = (const int*)d_in[2];
    const float* W0s = (const float*)d_in[3];
    const float* a0s = (const float*)d_in[4];
    const float* W0f = (const float*)d_in[5];
    const float* a0f = (const float*)d_in[6];
    const float* g0  = (const float*)d_in[7];
    const float* b0  = (const float*)d_in[8];
    const float* W1s = (const float*)d_in[9];
    const float* a1s = (const float*)d_in[10];
    const float* W1f = (const float*)d_in[11];
    const float* a1f = (const float*)d_in[12];
    const float* g1  = (const float*)d_in[13];
    const float* b1  = (const float*)d_in[14];
    float* out = (float*)d_out;

    float* xbuf = nullptr;
    cudaGetSymbolAddress((void**)&xbuf, g_xbuf);

    // CSR build (edge lists identical across layers -> build once per launch)
    k_zero_counts<<<(2*Nn + 255)/256, 256>>>();
    k_count<<<Ee/256, 256>>>(eis, 0);
    k_count<<<Ee/256, 256>>>(eif, 1);
    k_scan<<<1, 1024>>>(0);
    k_scan<<<1, 1024>>>(1);
    k_fill<<<Ee/256, 256>>>(eis, 0);
    k_fill<<<Ee/256, 256>>>(eif, 1);

    // layer 0
    run_conv(pred, W0s, a0s, 0, 1);
    run_conv(pred, W0f, a0f, 1, 0);
    k_ln<<<NT/8, dim3(32,8)>>>(pred, g0, b0, xbuf);

    // layer 1
    run_conv(xbuf, W1s, a1s, 0, 1);
    run_conv(xbuf, W1f, a1f, 1, 0);
    k_ln<<<NT/8, dim3(32,8)>>>(xbuf, g1, b1, out);
}

// round 2
// speedup vs baseline: 1.2898x; 1.2898x over previous
#include <cuda_runtime.h>

#define Nn 16384
#define Tt 4
#define Hh 64
#define Ee 262144
#define NT (Nn*Tt)
#define NEG_SLOPE 0.2f
#define LN_EPS 1e-5f

// -------- scratch (static device globals; no allocation) --------
__device__ __align__(16) float g_h[2][NT*Hh];     // per-edge-type transformed features
__device__ __align__(16) float g_logits[2][NT];   // leaky(dot(h,a)), layout [N][T]
__device__ __align__(16) float g_alpha[2][Ee*Tt]; // alpha in CSR order
__device__ __align__(16) float g_msum[NT*Hh];     // ms + mf
__device__ __align__(16) float g_xbuf[NT*Hh];     // layer-0 output
__device__ int g_off[2][Nn+1];
__device__ int g_cnt[2][Nn];
__device__ int g_csr[2][Ee];

// ---------------- CSR build ----------------
__global__ void k_zero_counts() {
    int i = blockIdx.x*blockDim.x + threadIdx.x;
    if (i < 2*Nn) ((int*)g_cnt)[i] = 0;
}

// both edge types in one kernel
__global__ void k_count2(const int* __restrict__ eis, const int* __restrict__ eif) {
    int i = blockIdx.x*blockDim.x + threadIdx.x;
    if (i < Ee)        atomicAdd(&g_cnt[0][eis[Ee + i]], 1);
    else if (i < 2*Ee) atomicAdd(&g_cnt[1][eif[i]], 1);   // eif[Ee + (i-Ee)]
}

// 2 blocks (one per edge type), 1024 threads x 16 elems, shuffle-based scan
__global__ void k_scan2() {
    __shared__ int warpsums[32];
    const int which = blockIdx.x;
    const int tid = threadIdx.x;
    const int lane = tid & 31, w = tid >> 5;
    const int base = tid * 16;
    int local[16];
    int s = 0;
    #pragma unroll
    for (int j = 0; j < 16; j++) { local[j] = s; s += g_cnt[which][base + j]; }
    // inclusive warp scan of s
    int v = s;
    #pragma unroll
    for (int off = 1; off < 32; off <<= 1) {
        int t = __shfl_up_sync(0xffffffffu, v, off);
        if (lane >= off) v += t;
    }
    if (lane == 31) warpsums[w] = v;
    __syncthreads();
    if (w == 0) {
        int x = warpsums[lane];
        #pragma unroll
        for (int off = 1; off < 32; off <<= 1) {
            int t = __shfl_up_sync(0xffffffffu, x, off);
            if (lane >= off) x += t;
        }
        warpsums[lane] = x;
    }
    __syncthreads();
    int pre = v - s + (w > 0 ? warpsums[w-1] : 0);   // exclusive prefix for this thread
    #pragma unroll
    for (int j = 0; j < 16; j++) {
        g_off[which][base + j] = pre + local[j];
        g_cnt[which][base + j] = 0;                   // becomes fill cursor
    }
    if (tid == 0) g_off[which][Nn] = warpsums[31];
}

__global__ void k_fill2(const int* __restrict__ eis, const int* __restrict__ eif) {
    int i = blockIdx.x*blockDim.x + threadIdx.x;
    int src, dst, which;
    if (i < Ee)        { which = 0; src = eis[i];      dst = eis[Ee + i]; }
    else if (i < 2*Ee) { which = 1; src = eif[i - Ee]; dst = eif[i]; }
    else return;
    int pos = g_off[which][dst] + atomicAdd(&g_cnt[which][dst], 1);
    g_csr[which][pos] = src;
}

// ---------------- fused GEMM: h_s = x@Ws, h_f = x@Wf, + logits ----------------
// block: 64 rows; blockDim (16,16); each thread 4 rows x 4 cols x 2 edge types.
__global__ void k_gemm2(const float* __restrict__ x,
                        const float* __restrict__ Ws, const float* __restrict__ as_g,
                        const float* __restrict__ Wf, const float* __restrict__ af_g) {
    __shared__ float xs[64*64];
    __shared__ float ws[2][64*64];
    const int tx = threadIdx.x;          // col group
    const int ty = threadIdx.y;          // row group
    const int tid = ty*16 + tx;
    const int rowBase = blockIdx.x * 64;

    const float4* Ws4 = (const float4*)Ws;
    const float4* Wf4 = (const float4*)Wf;
    float4* ws4s = (float4*)ws[0];
    float4* ws4f = (float4*)ws[1];
    #pragma unroll
    for (int i = tid; i < 1024; i += 256) { ws4s[i] = Ws4[i]; ws4f[i] = Wf4[i]; }
    const float4* x4 = (const float4*)(x + rowBase*64);
    float4* xs4 = (float4*)xs;
    #pragma unroll
    for (int i = tid; i < 1024; i += 256) xs4[i] = x4[i];
    __syncthreads();

    const int c0 = tx*4, r0 = ty*4;
    float accS[4][4] = {}, accF[4][4] = {};
    #pragma unroll 4
    for (int k = 0; k < 64; k++) {
        float4 wsv = *(const float4*)(&ws[0][k*64 + c0]);
        float4 wfv = *(const float4*)(&ws[1][k*64 + c0]);
        #pragma unroll
        for (int i = 0; i < 4; i++) {
            float xv = xs[(r0+i)*64 + k];   // broadcast across tx lanes
            accS[i][0] += xv*wsv.x; accS[i][1] += xv*wsv.y;
            accS[i][2] += xv*wsv.z; accS[i][3] += xv*wsv.w;
            accF[i][0] += xv*wfv.x; accF[i][1] += xv*wfv.y;
            accF[i][2] += xv*wfv.z; accF[i][3] += xv*wfv.w;
        }
    }

    float4 av = *(const float4*)(&as_g[c0]);
    float4 fv = *(const float4*)(&af_g[c0]);
    float pdS[4], pdF[4];
    #pragma unroll
    for (int i = 0; i < 4; i++) {
        int row = rowBase + r0 + i;
        *(float4*)(&g_h[0][row*64 + c0]) = make_float4(accS[i][0],accS[i][1],accS[i][2],accS[i][3]);
        *(float4*)(&g_h[1][row*64 + c0]) = make_float4(accF[i][0],accF[i][1],accF[i][2],accF[i][3]);
        pdS[i] = accS[i][0]*av.x + accS[i][1]*av.y + accS[i][2]*av.z + accS[i][3]*av.w;
        pdF[i] = accF[i][0]*fv.x + accF[i][1]*fv.y + accF[i][2]*fv.z + accF[i][3]*fv.w;
    }
    #pragma unroll
    for (int off = 8; off > 0; off >>= 1) {
        #pragma unroll
        for (int i = 0; i < 4; i++) {
            pdS[i] += __shfl_down_sync(0xffffffffu, pdS[i], off, 16);
            pdF[i] += __shfl_down_sync(0xffffffffu, pdF[i], off, 16);
        }
    }
    if (tx == 0) {
        #pragma unroll
        for (int i = 0; i < 4; i++) {
            float v = pdS[i];
            g_logits[0][rowBase + r0 + i] = (v > 0.f) ? v : NEG_SLOPE * v;
            v = pdF[i];
            g_logits[1][rowBase + r0 + i] = (v > 0.f) ? v : NEG_SLOPE * v;
        }
    }
}

// ---------------- per-node softmax -> alpha in CSR order (gridDim.y = which) ---
__global__ void k_softmax_alpha() {
    const int which = blockIdx.y;
    int n = blockIdx.x*blockDim.x + threadIdx.x;
    if (n >= Nn) return;
    int rs = g_off[which][n], re = g_off[which][n+1];
    if (rs == re) return;
    const int* __restrict__ srcs = g_csr[which];
    const float* __restrict__ lgt = g_logits[which];
    float4 mx = make_float4(-1e30f, -1e30f, -1e30f, -1e30f);
    for (int p = rs; p < re; p++) {
        int s = srcs[p];
        float4 lg = *(const float4*)&lgt[s*4];
        mx.x = fmaxf(mx.x, lg.x); mx.y = fmaxf(mx.y, lg.y);
        mx.z = fmaxf(mx.z, lg.z); mx.w = fmaxf(mx.w, lg.w);
    }
    float4 den = make_float4(0.f, 0.f, 0.f, 0.f);
    for (int p = rs; p < re; p++) {
        int s = srcs[p];
        float4 lg = *(const float4*)&lgt[s*4];
        den.x += __expf(lg.x - mx.x); den.y += __expf(lg.y - mx.y);
        den.z += __expf(lg.z - mx.z); den.w += __expf(lg.w - mx.w);
    }
    float4 rd = make_float4(1.f/den.x, 1.f/den.y, 1.f/den.z, 1.f/den.w);
    float* __restrict__ alp = g_alpha[which];
    for (int p = rs; p < re; p++) {
        int s = srcs[p];
        float4 lg = *(const float4*)&lgt[s*4];
        float4 al;
        al.x = __expf(lg.x - mx.x) * rd.x;
        al.y = __expf(lg.y - mx.y) * rd.y;
        al.z = __expf(lg.z - mx.z) * rd.z;
        al.w = __expf(lg.w - mx.w) * rd.w;
        *(float4*)&alp[p*4] = al;
    }
}

// ---------------- fused aggregation over BOTH edge types, single write -------
// blockDim (64,4): 4 nodes/block, 64 h-lanes, register accumulation, no atomics
__global__ void k_aggregate2() {
    const int node = blockIdx.x*4 + threadIdx.y;
    const int hh = threadIdx.x;
    float a0 = 0.f, a1 = 0.f, a2 = 0.f, a3 = 0.f;
    #pragma unroll
    for (int which = 0; which < 2; which++) {
        int rs = g_off[which][node], re = g_off[which][node+1];
        const int*   __restrict__ srcs = g_csr[which];
        const float* __restrict__ alp  = g_alpha[which];
        const float* __restrict__ hb   = g_h[which];
        for (int p = rs; p < re; p++) {
            int s = srcs[p];
            float4 al = *(const float4*)&alp[p*4];
            const float* hr = &hb[s*256];
            a0 += al.x * hr[hh];
            a1 += al.y * hr[64  + hh];
            a2 += al.z * hr[128 + hh];
            a3 += al.w * hr[192 + hh];
        }
    }
    float* o = &g_msum[node*256];
    o[hh] = a0; o[64+hh] = a1; o[128+hh] = a2; o[192+hh] = a3;
}

// ---------------- LayerNorm(x + 0.5*msum) ----------------
__global__ void k_ln(const float* __restrict__ xin,
                     const float* __restrict__ g,
                     const float* __restrict__ b,
                     float* __restrict__ out) {
    int row = blockIdx.x*8 + threadIdx.y;
    int lane = threadIdx.x;
    float2 xi = *(const float2*)&xin[row*64 + lane*2];
    float2 ms = *(const float2*)&g_msum[row*64 + lane*2];
    float v0 = xi.x + 0.5f*ms.x;
    float v1 = xi.y + 0.5f*ms.y;
    float s = v0 + v1, sq = v0*v0 + v1*v1;
    #pragma unroll
    for (int off = 16; off > 0; off >>= 1) {
        s  += __shfl_xor_sync(0xffffffffu, s,  off);
        sq += __shfl_xor_sync(0xffffffffu, sq, off);
    }
    float mean = s * (1.f/64.f);
    float var  = sq * (1.f/64.f) - mean*mean;
    float rstd = rsqrtf(var + LN_EPS);
    float2 gg = *(const float2*)&g[lane*2];
    float2 bb = *(const float2*)&b[lane*2];
    float2 o;
    o.x = (v0 - mean)*rstd*gg.x + bb.x;
    o.y = (v1 - mean)*rstd*gg.y + bb.y;
    *(float2*)&out[row*64 + lane*2] = o;
}

// ---------------- launch ----------------
static void run_layer(const float* x,
                      const float* Ws, const float* avs,
                      const float* Wf, const float* avf,
                      const float* g, const float* b, float* out) {
    k_gemm2<<<NT/64, dim3(16,16)>>>(x, Ws, avs, Wf, avf);
    k_softmax_alpha<<<dim3(Nn/256, 2), 256>>>();
    k_aggregate2<<<Nn/4, dim3(64,4)>>>();
    k_ln<<<NT/8, dim3(32,8)>>>(x, g, b, out);
}

extern "C" void kernel_launch(void* const* d_in, const int* in_sizes, int n_in,
                              void* d_out, int out_size) {
    const float* pred = (const float*)d_in[0];
    const int*   eis  = (const int*)d_in[1];
    const int*   eif  = (const int*)d_in[2];
    const float* W0s = (const float*)d_in[3];
    const float* a0s = (const float*)d_in[4];
    const float* W0f = (const float*)d_in[5];
    const float* a0f = (const float*)d_in[6];
    const float* g0  = (const float*)d_in[7];
    const float* b0  = (const float*)d_in[8];
    const float* W1s = (const float*)d_in[9];
    const float* a1s = (const float*)d_in[10];
    const float* W1f = (const float*)d_in[11];
    const float* a1f = (const float*)d_in[12];
    const float* g1  = (const float*)d_in[13];
    const float* b1  = (const float*)d_in[14];
    float* out = (float*)d_out;

    float* xbuf = nullptr;
    cudaGetSymbolAddress((void**)&xbuf, g_xbuf);

    // CSR build (edge lists shared by both layers -> build once per launch)
    k_zero_counts<<<(2*Nn + 255)/256, 256>>>();
    k_count2<<<2*Ee/256, 256>>>(eis, eif);
    k_scan2<<<2, 1024>>>();
    k_fill2<<<2*Ee/256, 256>>>(eis, eif);

    run_layer(pred, W0s, a0s, W0f, a0f, g0, b0, xbuf);
    run_layer(xbuf, W1s, a1s, W1f, a1f, g1, b1, out);
}

// round 3
// speedup vs baseline: 1.5997x; 1.2403x over previous
#include <cuda_runtime.h>
#include <cuda_fp16.h>

#define Nn 16384
#define Tt 4
#define Hh 64
#define Ee 262144
#define NT (Nn*Tt)
#define NEG_SLOPE 0.2f
#define LN_EPS 1e-5f

// -------- scratch (static device globals; no allocation) --------
__device__ __align__(16) __half g_h16[2][NT*Hh];  // fp16 transformed features
__device__ __align__(16) float g_logits[2][NT];   // leaky(dot(h,a)), layout [N][T]
__device__ __align__(16) float g_alpha[2][Ee*Tt]; // alpha in CSR order
__device__ __align__(16) float g_xbuf[NT*Hh];     // layer-0 output
__device__ int g_off[2][Nn+1];
__device__ int g_cnt[2][Nn];
__device__ int g_csr[2][Ee];

// ---------------- CSR build ----------------
__global__ void k_count2(const int* __restrict__ eis, const int* __restrict__ eif) {
    int i = blockIdx.x*blockDim.x + threadIdx.x;
    if (i < Ee)        atomicAdd(&g_cnt[0][eis[Ee + i]], 1);
    else if (i < 2*Ee) atomicAdd(&g_cnt[1][eif[i]], 1);   // eif[Ee + (i-Ee)]
}

// 2 blocks (one per edge type), 1024 threads x 16 elems, shuffle-based scan
__global__ void k_scan2() {
    __shared__ int warpsums[32];
    const int which = blockIdx.x;
    const int tid = threadIdx.x;
    const int lane = tid & 31, w = tid >> 5;
    const int base = tid * 16;
    int local[16];
    int s = 0;
    #pragma unroll
    for (int j = 0; j < 16; j++) { local[j] = s; s += g_cnt[which][base + j]; }
    int v = s;
    #pragma unroll
    for (int off = 1; off < 32; off <<= 1) {
        int t = __shfl_up_sync(0xffffffffu, v, off);
        if (lane >= off) v += t;
    }
    if (lane == 31) warpsums[w] = v;
    __syncthreads();
    if (w == 0) {
        int x = warpsums[lane];
        #pragma unroll
        for (int off = 1; off < 32; off <<= 1) {
            int t = __shfl_up_sync(0xffffffffu, x, off);
            if (lane >= off) x += t;
        }
        warpsums[lane] = x;
    }
    __syncthreads();
    int pre = v - s + (w > 0 ? warpsums[w-1] : 0);
    #pragma unroll
    for (int j = 0; j < 16; j++) {
        g_off[which][base + j] = pre + local[j];
        g_cnt[which][base + j] = 0;                   // becomes fill cursor
    }
    if (tid == 0) g_off[which][Nn] = warpsums[31];
}

__global__ void k_fill2(const int* __restrict__ eis, const int* __restrict__ eif) {
    int i = blockIdx.x*blockDim.x + threadIdx.x;
    int src, dst, which;
    if (i < Ee)        { which = 0; src = eis[i];      dst = eis[Ee + i]; }
    else if (i < 2*Ee) { which = 1; src = eif[i - Ee]; dst = eif[i]; }
    else return;
    int pos = g_off[which][dst] + atomicAdd(&g_cnt[which][dst], 1);
    g_csr[which][pos] = src;
}

// ---------------- fused GEMM: h_s = x@Ws, h_f = x@Wf (fp16 out) + logits -----
// block: 64 rows; blockDim (16,16); each thread 4 rows x 4 cols x 2 edge types.
__global__ void k_gemm2(const float* __restrict__ x,
                        const float* __restrict__ Ws, const float* __restrict__ as_g,
                        const float* __restrict__ Wf, const float* __restrict__ af_g) {
    __shared__ float xs[64*64];
    __shared__ float ws[2][64*64];
    const int tx = threadIdx.x;
    const int ty = threadIdx.y;
    const int tid = ty*16 + tx;
    const int rowBase = blockIdx.x * 64;

    const float4* Ws4 = (const float4*)Ws;
    const float4* Wf4 = (const float4*)Wf;
    float4* ws4s = (float4*)ws[0];
    float4* ws4f = (float4*)ws[1];
    #pragma unroll
    for (int i = tid; i < 1024; i += 256) { ws4s[i] = Ws4[i]; ws4f[i] = Wf4[i]; }
    const float4* x4 = (const float4*)(x + rowBase*64);
    float4* xs4 = (float4*)xs;
    #pragma unroll
    for (int i = tid; i < 1024; i += 256) xs4[i] = x4[i];
    __syncthreads();

    const int c0 = tx*4, r0 = ty*4;
    float accS[4][4] = {}, accF[4][4] = {};
    #pragma unroll 4
    for (int k = 0; k < 64; k++) {
        float4 wsv = *(const float4*)(&ws[0][k*64 + c0]);
        float4 wfv = *(const float4*)(&ws[1][k*64 + c0]);
        #pragma unroll
        for (int i = 0; i < 4; i++) {
            float xv = xs[(r0+i)*64 + k];
            accS[i][0] += xv*wsv.x; accS[i][1] += xv*wsv.y;
            accS[i][2] += xv*wsv.z; accS[i][3] += xv*wsv.w;
            accF[i][0] += xv*wfv.x; accF[i][1] += xv*wfv.y;
            accF[i][2] += xv*wfv.z; accF[i][3] += xv*wfv.w;
        }
    }

    float4 av = *(const float4*)(&as_g[c0]);
    float4 fv = *(const float4*)(&af_g[c0]);
    float pdS[4], pdF[4];
    #pragma unroll
    for (int i = 0; i < 4; i++) {
        int row = rowBase + r0 + i;
        __half2* ps = (__half2*)&g_h16[0][row*64 + c0];
        __half2* pf = (__half2*)&g_h16[1][row*64 + c0];
        ps[0] = __floats2half2_rn(accS[i][0], accS[i][1]);
        ps[1] = __floats2half2_rn(accS[i][2], accS[i][3]);
        pf[0] = __floats2half2_rn(accF[i][0], accF[i][1]);
        pf[1] = __floats2half2_rn(accF[i][2], accF[i][3]);
        pdS[i] = accS[i][0]*av.x + accS[i][1]*av.y + accS[i][2]*av.z + accS[i][3]*av.w;
        pdF[i] = accF[i][0]*fv.x + accF[i][1]*fv.y + accF[i][2]*fv.z + accF[i][3]*fv.w;
    }
    #pragma unroll
    for (int off = 8; off > 0; off >>= 1) {
        #pragma unroll
        for (int i = 0; i < 4; i++) {
            pdS[i] += __shfl_down_sync(0xffffffffu, pdS[i], off, 16);
            pdF[i] += __shfl_down_sync(0xffffffffu, pdF[i], off, 16);
        }
    }
    if (tx == 0) {
        #pragma unroll
        for (int i = 0; i < 4; i++) {
            float v = pdS[i];
            g_logits[0][rowBase + r0 + i] = (v > 0.f) ? v : NEG_SLOPE * v;
            v = pdF[i];
            g_logits[1][rowBase + r0 + i] = (v > 0.f) ? v : NEG_SLOPE * v;
        }
    }
}

// ---------------- per-node softmax -> alpha in CSR order (gridDim.y = which) --
__global__ void k_softmax_alpha() {
    const int which = blockIdx.y;
    int n = blockIdx.x*blockDim.x + threadIdx.x;
    if (n >= Nn) return;
    int rs = g_off[which][n], re = g_off[which][n+1];
    if (rs == re) return;
    const int* __restrict__ srcs = g_csr[which];
    const float* __restrict__ lgt = g_logits[which];
    float4 mx = make_float4(-1e30f, -1e30f, -1e30f, -1e30f);
    for (int p = rs; p < re; p++) {
        int s = srcs[p];
        float4 lg = *(const float4*)&lgt[s*4];
        mx.x = fmaxf(mx.x, lg.x); mx.y = fmaxf(mx.y, lg.y);
        mx.z = fmaxf(mx.z, lg.z); mx.w = fmaxf(mx.w, lg.w);
    }
    float4 den = make_float4(0.f, 0.f, 0.f, 0.f);
    for (int p = rs; p < re; p++) {
        int s = srcs[p];
        float4 lg = *(const float4*)&lgt[s*4];
        den.x += __expf(lg.x - mx.x); den.y += __expf(lg.y - mx.y);
        den.z += __expf(lg.z - mx.z); den.w += __expf(lg.w - mx.w);
    }
    float4 rd = make_float4(1.f/den.x, 1.f/den.y, 1.f/den.z, 1.f/den.w);
    float* __restrict__ alp = g_alpha[which];
    for (int p = rs; p < re; p++) {
        int s = srcs[p];
        float4 lg = *(const float4*)&lgt[s*4];
        float4 al;
        al.x = __expf(lg.x - mx.x) * rd.x;
        al.y = __expf(lg.y - mx.y) * rd.y;
        al.z = __expf(lg.z - mx.z) * rd.z;
        al.w = __expf(lg.w - mx.w) * rd.w;
        *(float4*)&alp[p*4] = al;
    }
}

// ------- fused aggregation (both edge types) + residual + LayerNorm ----------
// blockDim (32,8): one warp per node; lane owns 2 h-columns (half2).
__global__ void k_agg_ln(const float* __restrict__ xin,
                         const float* __restrict__ g,
                         const float* __restrict__ b,
                         float* __restrict__ out) {
    const int node = blockIdx.x*8 + threadIdx.y;
    const int l = threadIdx.x;
    float2 acc[4] = {};
    #pragma unroll
    for (int which = 0; which < 2; which++) {
        int rs = g_off[which][node], re = g_off[which][node+1];
        const int*    __restrict__ srcs = g_csr[which];
        const float*  __restrict__ alp  = g_alpha[which];
        const __half2* __restrict__ hb  = (const __half2*)g_h16[which];
        for (int p = rs; p < re; p++) {
            int s = srcs[p];
            float4 al = *(const float4*)&alp[p*4];
            const __half2* hr = hb + s*128 + l;     // row = 256 halves = 128 half2
            float2 f0 = __half22float2(hr[0]);
            float2 f1 = __half22float2(hr[32]);
            float2 f2 = __half22float2(hr[64]);
            float2 f3 = __half22float2(hr[96]);
            acc[0].x += al.x*f0.x; acc[0].y += al.x*f0.y;
            acc[1].x += al.y*f1.x; acc[1].y += al.y*f1.y;
            acc[2].x += al.z*f2.x; acc[2].y += al.z*f2.y;
            acc[3].x += al.w*f3.x; acc[3].y += al.w*f3.y;
        }
    }
    float2 gg = *(const float2*)&g[l*2];
    float2 bb = *(const float2*)&b[l*2];
    #pragma unroll
    for (int t = 0; t < 4; t++) {
        float2 xi = *(const float2*)&xin[(node*4 + t)*64 + l*2];
        float v0 = xi.x + 0.5f*acc[t].x;
        float v1 = xi.y + 0.5f*acc[t].y;
        float s = v0 + v1, sq = v0*v0 + v1*v1;
        #pragma unroll
        for (int off = 16; off > 0; off >>= 1) {
            s  += __shfl_xor_sync(0xffffffffu, s,  off);
            sq += __shfl_xor_sync(0xffffffffu, sq, off);
        }
        float mean = s * (1.f/64.f);
        float var  = sq * (1.f/64.f) - mean*mean;
        float rstd = rsqrtf(var + LN_EPS);
        float2 o;
        o.x = (v0 - mean)*rstd*gg.x + bb.x;
        o.y = (v1 - mean)*rstd*gg.y + bb.y;
        *(float2*)&out[(node*4 + t)*64 + l*2] = o;
    }
}

// ---------------- launch ----------------
static void run_layer(const float* x,
                      const float* Ws, const float* avs,
                      const float* Wf, const float* avf,
                      const float* g, const float* b, float* out) {
    k_gemm2<<<NT/64, dim3(16,16)>>>(x, Ws, avs, Wf, avf);
    k_softmax_alpha<<<dim3(Nn/256, 2), 256>>>();
    k_agg_ln<<<Nn/8, dim3(32,8)>>>(x, g, b, out);
}

extern "C" void kernel_launch(void* const* d_in, const int* in_sizes, int n_in,
                              void* d_out, int out_size) {
    const float* pred = (const float*)d_in[0];
    const int*   eis  = (const int*)d_in[1];
    const int*   eif  = (const int*)d_in[2];
    const float* W0s = (const float*)d_in[3];
    const float* a0s = (const float*)d_in[4];
    const float* W0f = (const float*)d_in[5];
    const float* a0f = (const float*)d_in[6];
    const float* g0  = (const float*)d_in[7];
    const float* b0  = (const float*)d_in[8];
    const float* W1s = (const float*)d_in[9];
    const float* a1s = (const float*)d_in[10];
    const float* W1f = (const float*)d_in[11];
    const float* a1f = (const float*)d_in[12];
    const float* g1  = (const float*)d_in[13];
    const float* b1  = (const float*)d_in[14];
    float* out = (float*)d_out;

    float* xbuf = nullptr;
    cudaGetSymbolAddress((void**)&xbuf, g_xbuf);
    int* cntp = nullptr;
    cudaGetSymbolAddress((void**)&cntp, g_cnt);

    // CSR build (edge lists shared by both layers -> build once per launch)
    cudaMemsetAsync(cntp, 0, 2*Nn*sizeof(int));
    k_count2<<<2*Ee/256, 256>>>(eis, eif);
    k_scan2<<<2, 1024>>>();
    k_fill2<<<2*Ee/256, 256>>>(eis, eif);

    run_layer(pred, W0s, a0s, W0f, a0f, g0, b0, xbuf);
    run_layer(xbuf, W1s, a1s, W1f, a1f, g1, b1, out);
}

// round 4
// speedup vs baseline: 1.8744x; 1.1718x over previous
#include <cuda_runtime.h>
#include <cuda_fp16.h>

#define Nn 16384
#define Tt 4
#define Hh 64
#define Ee 262144
#define NT (Nn*Tt)
#define NEG_SLOPE 0.2f
#define LN_EPS 1e-5f

// -------- scratch (static device globals; no allocation) --------
__device__ __align__(16) __half g_h16[2][NT*Hh];  // fp16 transformed features
__device__ __align__(16) float g_logits[2][NT];   // leaky(dot(h,a)), layout [N][T]
__device__ __align__(16) float g_xbuf[NT*Hh];     // layer-0 output
__device__ int g_off[2][Nn+1];
__device__ int g_cnt[2][Nn];
__device__ int g_csr[2][Ee];

// ---------------- CSR build ----------------
__global__ void k_count2(const int* __restrict__ eis, const int* __restrict__ eif) {
    int i = blockIdx.x*blockDim.x + threadIdx.x;
    if (i < Ee)        atomicAdd(&g_cnt[0][eis[Ee + i]], 1);
    else if (i < 2*Ee) atomicAdd(&g_cnt[1][eif[i]], 1);   // eif[Ee + (i-Ee)]
}

__global__ void k_scan2() {
    __shared__ int warpsums[32];
    const int which = blockIdx.x;
    const int tid = threadIdx.x;
    const int lane = tid & 31, w = tid >> 5;
    const int base = tid * 16;
    int local[16];
    int s = 0;
    #pragma unroll
    for (int j = 0; j < 16; j++) { local[j] = s; s += g_cnt[which][base + j]; }
    int v = s;
    #pragma unroll
    for (int off = 1; off < 32; off <<= 1) {
        int t = __shfl_up_sync(0xffffffffu, v, off);
        if (lane >= off) v += t;
    }
    if (lane == 31) warpsums[w] = v;
    __syncthreads();
    if (w == 0) {
        int x = warpsums[lane];
        #pragma unroll
        for (int off = 1; off < 32; off <<= 1) {
            int t = __shfl_up_sync(0xffffffffu, x, off);
            if (lane >= off) x += t;
        }
        warpsums[lane] = x;
    }
    __syncthreads();
    int pre = v - s + (w > 0 ? warpsums[w-1] : 0);
    #pragma unroll
    for (int j = 0; j < 16; j++) {
        g_off[which][base + j] = pre + local[j];
        g_cnt[which][base + j] = 0;                   // becomes fill cursor
    }
    if (tid == 0) g_off[which][Nn] = warpsums[31];
}

__global__ void k_fill2(const int* __restrict__ eis, const int* __restrict__ eif) {
    int i = blockIdx.x*blockDim.x + threadIdx.x;
    int src, dst, which;
    if (i < Ee)        { which = 0; src = eis[i];      dst = eis[Ee + i]; }
    else if (i < 2*Ee) { which = 1; src = eif[i - Ee]; dst = eif[i]; }
    else return;
    int pos = g_off[which][dst] + atomicAdd(&g_cnt[which][dst], 1);
    g_csr[which][pos] = src;
}

// ---------------- fused GEMM: h_s = x@Ws, h_f = x@Wf (fp16 out) + logits -----
// 64-row tile, blockDim (16,8) = 128 threads; thread = 8 rows x 4 cols x 2 mats.
__global__ __launch_bounds__(128) void k_gemm2(
        const float* __restrict__ x,
        const float* __restrict__ Ws, const float* __restrict__ as_g,
        const float* __restrict__ Wf, const float* __restrict__ af_g) {
    __shared__ float xs[64*64];        // 16 KB
    __shared__ float ws[2][64*64];     // 32 KB  (total 48 KB static)
    const int tx = threadIdx.x;        // 0..15 col group
    const int ty = threadIdx.y;        // 0..7  row group
    const int tid = ty*16 + tx;        // 0..127
    const int rowBase = blockIdx.x * 64;

    const float4* Ws4 = (const float4*)Ws;
    const float4* Wf4 = (const float4*)Wf;
    float4* ws4s = (float4*)ws[0];
    float4* ws4f = (float4*)ws[1];
    #pragma unroll
    for (int i = tid; i < 1024; i += 128) { ws4s[i] = Ws4[i]; ws4f[i] = Wf4[i]; }
    const float4* x4 = (const float4*)(x + rowBase*64);
    float4* xs4 = (float4*)xs;
    #pragma unroll
    for (int i = tid; i < 1024; i += 128) xs4[i] = x4[i];
    __syncthreads();

    const int c0 = tx*4, r0 = ty*8;
    float accS[8][4] = {}, accF[8][4] = {};
    #pragma unroll 4
    for (int k = 0; k < 64; k++) {
        float4 wsv = *(const float4*)(&ws[0][k*64 + c0]);
        float4 wfv = *(const float4*)(&ws[1][k*64 + c0]);
        #pragma unroll
        for (int i = 0; i < 8; i++) {
            float xv = xs[(r0+i)*64 + k];
            accS[i][0] += xv*wsv.x; accS[i][1] += xv*wsv.y;
            accS[i][2] += xv*wsv.z; accS[i][3] += xv*wsv.w;
            accF[i][0] += xv*wfv.x; accF[i][1] += xv*wfv.y;
            accF[i][2] += xv*wfv.z; accF[i][3] += xv*wfv.w;
        }
    }

    float4 av = *(const float4*)(&as_g[c0]);
    float4 fv = *(const float4*)(&af_g[c0]);
    float pdS[8], pdF[8];
    #pragma unroll
    for (int i = 0; i < 8; i++) {
        int row = rowBase + r0 + i;
        __half2* ps = (__half2*)&g_h16[0][row*64 + c0];
        __half2* pf = (__half2*)&g_h16[1][row*64 + c0];
        ps[0] = __floats2half2_rn(accS[i][0], accS[i][1]);
        ps[1] = __floats2half2_rn(accS[i][2], accS[i][3]);
        pf[0] = __floats2half2_rn(accF[i][0], accF[i][1]);
        pf[1] = __floats2half2_rn(accF[i][2], accF[i][3]);
        pdS[i] = accS[i][0]*av.x + accS[i][1]*av.y + accS[i][2]*av.z + accS[i][3]*av.w;
        pdF[i] = accF[i][0]*fv.x + accF[i][1]*fv.y + accF[i][2]*fv.z + accF[i][3]*fv.w;
    }
    #pragma unroll
    for (int off = 8; off > 0; off >>= 1) {
        #pragma unroll
        for (int i = 0; i < 8; i++) {
            pdS[i] += __shfl_down_sync(0xffffffffu, pdS[i], off, 16);
            pdF[i] += __shfl_down_sync(0xffffffffu, pdF[i], off, 16);
        }
    }
    if (tx == 0) {
        #pragma unroll
        for (int i = 0; i < 8; i++) {
            float v = pdS[i];
            g_logits[0][rowBase + r0 + i] = (v > 0.f) ? v : NEG_SLOPE * v;
            v = pdF[i];
            g_logits[1][rowBase + r0 + i] = (v > 0.f) ? v : NEG_SLOPE * v;
        }
    }
}

// ------- fully fused: softmax + aggregation (both edge types) + LN ----------
// blockDim (32,8): one warp per node; lane owns 2 h-columns (half2).
__global__ void k_agg_ln(const float* __restrict__ xin,
                         const float* __restrict__ g,
                         const float* __restrict__ b,
                         float* __restrict__ out) {
    __shared__ float s_alpha[8][32][4];
    __shared__ int   s_src[8][32];
    const int node = blockIdx.x*8 + threadIdx.y;
    const int ty = threadIdx.y;
    const int l = threadIdx.x;
    float2 acc[4] = {};
    #pragma unroll
    for (int which = 0; which < 2; which++) {
        const int rs = g_off[which][node], re = g_off[which][node+1];
        const int*    __restrict__ srcs = g_csr[which];
        const float*  __restrict__ lgt  = g_logits[which];
        const __half2* __restrict__ hb  = (const __half2*)g_h16[which];

        // --- softmax stats, lane-parallel over edges ---
        float4 mx = make_float4(-1e30f, -1e30f, -1e30f, -1e30f);
        for (int p = rs + l; p < re; p += 32) {
            float4 lg = *(const float4*)&lgt[srcs[p]*4];
            mx.x = fmaxf(mx.x, lg.x); mx.y = fmaxf(mx.y, lg.y);
            mx.z = fmaxf(mx.z, lg.z); mx.w = fmaxf(mx.w, lg.w);
        }
        #pragma unroll
        for (int off = 16; off > 0; off >>= 1) {
            mx.x = fmaxf(mx.x, __shfl_xor_sync(0xffffffffu, mx.x, off));
            mx.y = fmaxf(mx.y, __shfl_xor_sync(0xffffffffu, mx.y, off));
            mx.z = fmaxf(mx.z, __shfl_xor_sync(0xffffffffu, mx.z, off));
            mx.w = fmaxf(mx.w, __shfl_xor_sync(0xffffffffu, mx.w, off));
        }
        float4 den = make_float4(0.f, 0.f, 0.f, 0.f);
        for (int p = rs + l; p < re; p += 32) {
            float4 lg = *(const float4*)&lgt[srcs[p]*4];
            den.x += __expf(lg.x - mx.x); den.y += __expf(lg.y - mx.y);
            den.z += __expf(lg.z - mx.z); den.w += __expf(lg.w - mx.w);
        }
        #pragma unroll
        for (int off = 16; off > 0; off >>= 1) {
            den.x += __shfl_xor_sync(0xffffffffu, den.x, off);
            den.y += __shfl_xor_sync(0xffffffffu, den.y, off);
            den.z += __shfl_xor_sync(0xffffffffu, den.z, off);
            den.w += __shfl_xor_sync(0xffffffffu, den.w, off);
        }
        float4 rd = make_float4(1.f/den.x, 1.f/den.y, 1.f/den.z, 1.f/den.w);

        // --- aggregation in 32-edge chunks; alpha staged through smem ---
        for (int base = rs; base < re; base += 32) {
            int p = base + l;
            if (p < re) {
                int s = srcs[p];
                float4 lg = *(const float4*)&lgt[s*4];
                s_src[ty][l] = s;
                s_alpha[ty][l][0] = __expf(lg.x - mx.x) * rd.x;
                s_alpha[ty][l][1] = __expf(lg.y - mx.y) * rd.y;
                s_alpha[ty][l][2] = __expf(lg.z - mx.z) * rd.z;
                s_alpha[ty][l][3] = __expf(lg.w - mx.w) * rd.w;
            }
            __syncwarp();
            int cnt = min(32, re - base);
            for (int j = 0; j < cnt; j++) {
                int s = s_src[ty][j];
                float4 al = *(const float4*)s_alpha[ty][j];
                const __half2* hr = hb + s*128 + l;   // row = 256 halves
                float2 f0 = __half22float2(hr[0]);
                float2 f1 = __half22float2(hr[32]);
                float2 f2 = __half22float2(hr[64]);
                float2 f3 = __half22float2(hr[96]);
                acc[0].x += al.x*f0.x; acc[0].y += al.x*f0.y;
                acc[1].x += al.y*f1.x; acc[1].y += al.y*f1.y;
                acc[2].x += al.z*f2.x; acc[2].y += al.z*f2.y;
                acc[3].x += al.w*f3.x; acc[3].y += al.w*f3.y;
            }
            __syncwarp();
        }
    }

    // --- residual + LayerNorm ---
    float2 gg = *(const float2*)&g[l*2];
    float2 bb = *(const float2*)&b[l*2];
    #pragma unroll
    for (int t = 0; t < 4; t++) {
        float2 xi = *(const float2*)&xin[(node*4 + t)*64 + l*2];
        float v0 = xi.x + 0.5f*acc[t].x;
        float v1 = xi.y + 0.5f*acc[t].y;
        float s = v0 + v1, sq = v0*v0 + v1*v1;
        #pragma unroll
        for (int off = 16; off > 0; off >>= 1) {
            s  += __shfl_xor_sync(0xffffffffu, s,  off);
            sq += __shfl_xor_sync(0xffffffffu, sq, off);
        }
        float mean = s * (1.f/64.f);
        float var  = sq * (1.f/64.f) - mean*mean;
        float rstd = rsqrtf(var + LN_EPS);
        float2 o;
        o.x = (v0 - mean)*rstd*gg.x + bb.x;
        o.y = (v1 - mean)*rstd*gg.y + bb.y;
        *(float2*)&out[(node*4 + t)*64 + l*2] = o;
    }
}

// ---------------- launch ----------------
static void run_layer(const float* x,
                      const float* Ws, const float* avs,
                      const float* Wf, const float* avf,
                      const float* g, const float* b, float* out) {
    k_gemm2<<<NT/64, dim3(16,8)>>>(x, Ws, avs, Wf, avf);
    k_agg_ln<<<Nn/8, dim3(32,8)>>>(x, g, b, out);
}

extern "C" void kernel_launch(void* const* d_in, const int* in_sizes, int n_in,
                              void* d_out, int out_size) {
    const float* pred = (const float*)d_in[0];
    const int*   eis  = (const int*)d_in[1];
    const int*   eif  = (const int*)d_in[2];
    const float* W0s = (const float*)d_in[3];
    const float* a0s = (const float*)d_in[4];
    const float* W0f = (const float*)d_in[5];
    const float* a0f = (const float*)d_in[6];
    const float* g0  = (const float*)d_in[7];
    const float* b0  = (const float*)d_in[8];
    const float* W1s = (const float*)d_in[9];
    const float* a1s = (const float*)d_in[10];
    const float* W1f = (const float*)d_in[11];
    const float* a1f = (const float*)d_in[12];
    const float* g1  = (const float*)d_in[13];
    const float* b1  = (const float*)d_in[14];
    float* out = (float*)d_out;

    float* xbuf = nullptr;
    cudaGetSymbolAddress((void**)&xbuf, g_xbuf);
    int* cntp = nullptr;
    cudaGetSymbolAddress((void**)&cntp, g_cnt);

    // CSR build (edge lists shared by both layers -> build once per launch)
    cudaMemsetAsync(cntp, 0, 2*Nn*sizeof(int));
    k_count2<<<2*Ee/256, 256>>>(eis, eif);
    k_scan2<<<2, 1024>>>();
    k_fill2<<<2*Ee/256, 256>>>(eis, eif);

    run_layer(pred, W0s, a0s, W0f, a0f, g0, b0, xbuf);
    run_layer(xbuf, W1s, a1s, W1f, a1f, g1, b1, out);
}